// round 5
// baseline (speedup 1.0000x reference)
#include <cuda_runtime.h>

// ---------------------------------------------------------------------------
// unit_aagcn: N=64, C=OC=64, T=300, V=25, S=3, IC=16
// FFMA2-packed. k1: wide-LDS rewrite (i-tiling + transposed M layouts).
// ---------------------------------------------------------------------------

#define N_  64
#define C_  64
#define T_  300
#define V_  25
#define S_  3
#define IC_ 16

#define TCH1 3           // K1 t-chunks (100 t per block, 8 at a time + peel)
#define T1   (T_ / TCH1) // 100
#define NPAIR (T_ / 2)   // 150 t-pairs per n
#define NITEMS (N_ * NPAIR) // 9600 k3 work items

typedef unsigned long long u64;

__device__ float g_Mpart[N_ * S_ * TCH1 * V_ * V_];
__device__ u64   g_Aa2[N_ * S_ * V_ * V_];   // [n][s][v][w] {a,a}

__device__ __forceinline__ u64 pack2(float lo, float hi) {
    u64 r; asm("mov.b64 %0, {%1, %2};" : "=l"(r) : "f"(lo), "f"(hi)); return r;
}
__device__ __forceinline__ u64 bcast2(float v) {
    u64 r; asm("mov.b64 %0, {%1, %1};" : "=l"(r) : "f"(v)); return r;
}
__device__ __forceinline__ void unpack2(u64 p, float& lo, float& hi) {
    asm("mov.b64 {%0, %1}, %2;" : "=f"(lo), "=f"(hi) : "l"(p));
}
__device__ __forceinline__ u64 ffma2(u64 a, u64 b, u64 c) {
    u64 d; asm("fma.rn.f32x2 %0, %1, %2, %3;" : "=l"(d) : "l"(a), "l"(b), "l"(c));
    return d;
}
__device__ __forceinline__ float tanh_hw(float x) {
    float y; asm("tanh.approx.f32 %0, %1;" : "=f"(y) : "f"(x)); return y;
}

// ---------------------------------------------------------------------------
// K1: one block per (t-chunk, s, n). 160 threads. 8 t per iteration (+4t peel).
// smem (dynamic, 96.9 KB):
//   Wa2/Wb2 : u64[64*16]  [c][i] dup'd            (8 KB each)
//   xs2     : u64[64*100] [c][pr*25+v] t-pairs    (51.2 KB)
//   a2T/b2T : u64[100*18] [(p*25+v)][i] pad 18    (14.4 KB each)
// ---------------------------------------------------------------------------
#define K1_OFF_WA  0
#define K1_OFF_WB  8192
#define K1_OFF_X   16384
#define K1_OFF_A   (16384 + 51200)
#define K1_OFF_B   (K1_OFF_A + 14400)
#define K1_OFF_BN  (K1_OFF_B + 14400)
#define SMEM1      (K1_OFF_BN + 256)

__global__ void __launch_bounds__(160)
k1_conv_M(const float* __restrict__ x,
          const float* __restrict__ wa, const float* __restrict__ ba,
          const float* __restrict__ wb, const float* __restrict__ bb,
          const float* __restrict__ ga, const float* __restrict__ bea,
          const float* __restrict__ ma, const float* __restrict__ va,
          const float* __restrict__ gb, const float* __restrict__ beb,
          const float* __restrict__ mb, const float* __restrict__ vb)
{
    extern __shared__ char sm1[];
    u64* Wa2 = (u64*)(sm1 + K1_OFF_WA);
    u64* Wb2 = (u64*)(sm1 + K1_OFF_WB);
    u64* xs2 = (u64*)(sm1 + K1_OFF_X);
    u64* a2T = (u64*)(sm1 + K1_OFF_A);
    u64* b2T = (u64*)(sm1 + K1_OFF_B);
    float* sA = (float*)(sm1 + K1_OFF_BN);
    float* cA = sA + IC_;
    float* sB = sA + 2 * IC_;
    float* cB = sA + 3 * IC_;

    const int tc = blockIdx.x;
    const int s  = blockIdx.y;
    const int n  = blockIdx.z;
    const int tid = threadIdx.x;

    for (int idx = tid; idx < IC_ * C_; idx += 160) {
        int c = idx >> 4, i = idx & 15;
        Wa2[idx] = bcast2(wa[(s * IC_ + i) * C_ + c]);
        Wb2[idx] = bcast2(wb[(s * IC_ + i) * C_ + c]);
    }
    if (tid < IC_) {
        int i = tid;
        float sa = ga[s * IC_ + i] * rsqrtf(va[s * IC_ + i] + 1e-5f);
        sA[i] = sa;
        cA[i] = sa * (ba[s * IC_ + i] - ma[s * IC_ + i]) + bea[s * IC_ + i];
        float sb = gb[s * IC_ + i] * rsqrtf(vb[s * IC_ + i] + 1e-5f);
        sB[i] = sb;
        cB[i] = sb * (bb[s * IC_ + i] - mb[s * IC_ + i]) + beb[s * IC_ + i];
    }

    // conv mapping: 160 = 4 pr (t-pairs) x 8 ig (i-pairs) x 5 vg
    const int pr = tid / 40;
    const int r  = tid % 40;
    const int ig = r / 5;
    const int vg = r % 5;
    // M mapping (tid < 125): (vv, wg)
    const int vv = tid / 5;
    const int wg = tid % 5;

    u64 m2[5] = {0ull, 0ull, 0ull, 0ull, 0ull};
    const int t0 = tc * T1;

    for (int tp = 0; tp < T1; tp += 8) {
        const int npr = (T1 - tp >= 8) ? 4 : 2;
        __syncthreads();   // prev M reads of a2T/b2T + prev conv reads of xs2 done

        // load x[n, :, t..t+2*npr-1, :] as packed t-pairs
        if (npr == 4) {
            #pragma unroll
            for (int rr = 0; rr < 40; rr++) {
                int idx = tid + rr * 160;
                int c = idx / 100, rm = idx % 100;
                int p = rm / 25, v = rm % 25;
                const float* gp = x + ((n * C_ + c) * T_ + t0 + tp + 2 * p) * V_ + v;
                xs2[c * 100 + rm] = pack2(gp[0], gp[V_]);
            }
        } else {
            #pragma unroll
            for (int rr = 0; rr < 20; rr++) {
                int idx = tid + rr * 160;
                int c = idx / 50, rm = idx % 50;
                int p = rm / 25, v = rm % 25;
                const float* gp = x + ((n * C_ + c) * T_ + t0 + tp + 2 * p) * V_ + v;
                xs2[c * 100 + p * 25 + v] = pack2(gp[0], gp[V_]);
            }
        }
        __syncthreads();   // xs2 ready

        // conv: each thread computes 2 i-channels x 5 v for its t-pair
        if (pr < npr) {
            u64 acca[2][5], accb[2][5];
            #pragma unroll
            for (int j = 0; j < 2; j++)
                #pragma unroll
                for (int k = 0; k < 5; k++) { acca[j][k] = 0ull; accb[j][k] = 0ull; }

            const u64* xrow = xs2 + pr * 25 + vg * 5;
            const u64* wab  = Wa2 + ig * 2;
            const u64* wbb  = Wb2 + ig * 2;
            #pragma unroll 4
            for (int c = 0; c < C_; c++) {
                ulonglong2 wa2 = *(const ulonglong2*)(wab + c * 16);
                ulonglong2 wb2 = *(const ulonglong2*)(wbb + c * 16);
                #pragma unroll
                for (int k = 0; k < 5; k++) {
                    u64 xv = xrow[c * 100 + k];
                    acca[0][k] = ffma2(wa2.x, xv, acca[0][k]);
                    acca[1][k] = ffma2(wa2.y, xv, acca[1][k]);
                    accb[0][k] = ffma2(wb2.x, xv, accb[0][k]);
                    accb[1][k] = ffma2(wb2.y, xv, accb[1][k]);
                }
            }
            const int i0 = ig * 2, i1 = i0 + 1;
            float sa0 = sA[i0], ca0 = cA[i0], sa1 = sA[i1], ca1 = cA[i1];
            float sb0 = sB[i0], cb0 = cB[i0], sb1 = sB[i1], cb1 = cB[i1];
            u64* arow = a2T + (pr * 25 + vg * 5) * 18 + ig * 2;
            u64* brow = b2T + (pr * 25 + vg * 5) * 18 + ig * 2;
            #pragma unroll
            for (int k = 0; k < 5; k++) {
                float lo, hi;
                ulonglong2 av, bv;
                unpack2(acca[0][k], lo, hi);
                av.x = pack2(tanh_hw(fmaf(sa0, lo, ca0)), tanh_hw(fmaf(sa0, hi, ca0)));
                unpack2(acca[1][k], lo, hi);
                av.y = pack2(tanh_hw(fmaf(sa1, lo, ca1)), tanh_hw(fmaf(sa1, hi, ca1)));
                unpack2(accb[0][k], lo, hi);
                bv.x = pack2(tanh_hw(fmaf(sb0, lo, cb0)), tanh_hw(fmaf(sb0, hi, cb0)));
                unpack2(accb[1][k], lo, hi);
                bv.y = pack2(tanh_hw(fmaf(sb1, lo, cb1)), tanh_hw(fmaf(sb1, hi, cb1)));
                *(ulonglong2*)(arow + k * 18) = av;
                *(ulonglong2*)(brow + k * 18) = bv;
            }
        }
        __syncthreads();   // a2T/b2T ready

        // M: m[v][w] += sum_{p,i} a[p][v][i] * b[p][w][i]
        if (tid < 125) {
            for (int p = 0; p < npr; p++) {
                const u64* arow = a2T + (p * 25 + vv) * 18;
                const u64* bbase = b2T + (p * 25 + wg * 5) * 18;
                #pragma unroll
                for (int ip = 0; ip < 8; ip++) {
                    ulonglong2 av = *(const ulonglong2*)(arow + ip * 2);
                    #pragma unroll
                    for (int k = 0; k < 5; k++) {
                        ulonglong2 bv = *(const ulonglong2*)(bbase + k * 18 + ip * 2);
                        m2[k] = ffma2(av.x, bv.x, m2[k]);
                        m2[k] = ffma2(av.y, bv.y, m2[k]);
                    }
                }
            }
        }
    }

    if (tid < 125) {
        float* dst = g_Mpart + ((((n * S_ + s) * TCH1 + tc) * V_ + vv) * V_) + wg * 5;
        #pragma unroll
        for (int k = 0; k < 5; k++) {
            float lo, hi;
            unpack2(m2[k], lo, hi);
            dst[k] = lo + hi;
        }
    }
}

// ---------------------------------------------------------------------------
// k2: A_adp[n][s][v][w] duplicated u64 from M partials. One block per n.
// ---------------------------------------------------------------------------
__global__ void __launch_bounds__(256)
k2_adp(const float* __restrict__ A, const float* __restrict__ alpha)
{
    const int n = blockIdx.x;
    const float al = alpha[0];
    for (int idx = threadIdx.x; idx < S_ * V_ * V_; idx += 256) {
        const float* mp = g_Mpart + (n * S_ * TCH1) * (V_ * V_) +
                          (idx / (V_ * V_)) * TCH1 * (V_ * V_) + (idx % (V_ * V_));
        float msum = 0.f;
        #pragma unroll
        for (int p = 0; p < TCH1; p++) msum += mp[p * (V_ * V_)];
        float val = A[idx] + tanhf(msum * (1.0f / (IC_ * T_))) * al;
        g_Aa2[n * (S_ * V_ * V_) + idx] = bcast2(val);
    }
}

// ---------------------------------------------------------------------------
// K3: persistent blocks over flattened (n, t-pair) items. 256 threads.
// smem: WdT 49152 + xs2[2] 25600 + zs2 38400 = 113152 B -> 2 CTAs/SM.
// ---------------------------------------------------------------------------
#define OFF_WDT   0
#define OFF_XS    49152
#define OFF_ZS    (49152 + 25600)
#define SMEM3     (OFF_ZS + 38400)

__global__ void __launch_bounds__(256, 2)
k3_out(const float* __restrict__ x,
       const float* __restrict__ wd, const float* __restrict__ bd,
       const float* __restrict__ bng, const float* __restrict__ bnb,
       const float* __restrict__ bnm, const float* __restrict__ bnv,
       float* __restrict__ out)
{
    extern __shared__ char smem[];
    float* WdT = (float*)(smem + OFF_WDT);   // [s][c][o]
    u64*   xsA = (u64*)  (smem + OFF_XS);    // two buffers of [c][v] t-pairs
    u64*   zs2 = (u64*)  (smem + OFF_ZS);    // [(s*25+v)][o] packed

    const int tid  = threadIdx.x;
    const int nblk = gridDim.x;

    for (int idx = tid; idx < S_ * C_ * C_; idx += 256) {
        int s = idx >> 12, o = (idx >> 6) & 63, c = idx & 63;
        WdT[(s << 12) + (c << 6) + o] = wd[idx];
    }

    const int sZ  = tid / 80;
    const int rZ  = tid % 80;
    const int ogZ = rZ & 15;
    const int vgZ = rZ >> 4;
    const int ogY = tid & 31;
    const int wgY = tid >> 5;

    float sc0 = 0.f, sh0 = 0.f, sc1 = 0.f, sh1 = 0.f;
    if (tid < 160) {
        int o0 = ogY * 2, o1 = o0 + 1;
        sc0 = bng[o0] * rsqrtf(bnv[o0] + 1e-5f);
        sh0 = bnb[o0] + sc0 * (bd[o0] + bd[C_ + o0] + bd[2 * C_ + o0] - bnm[o0]);
        sc1 = bng[o1] * rsqrtf(bnv[o1] + 1e-5f);
        sh1 = bnb[o1] + sc1 * (bd[o1] + bd[C_ + o1] + bd[2 * C_ + o1] - bnm[o1]);
    }

    int j = blockIdx.x;
    if (j >= NITEMS) return;

    u64 px[7];
    {
        int n = j / NPAIR, t = (j % NPAIR) * 2;
        const float* xb = x + (n * C_ * T_ + t) * V_;
        #pragma unroll
        for (int rr = 0; rr < 7; rr++) {
            int idx = tid + rr * 256;
            if (idx < C_ * V_) {
                int c = idx / V_, v = idx % V_;
                const float* gp = xb + c * (T_ * V_) + v;
                px[rr] = pack2(gp[0], gp[V_]);
            }
        }
    }

    int buf = 0;
    for (; j < NITEMS; j += nblk) {
        const int n = j / NPAIR;
        const int t = (j % NPAIR) * 2;
        u64* xs2 = xsA + buf * (C_ * V_);

        #pragma unroll
        for (int rr = 0; rr < 7; rr++) {
            int idx = tid + rr * 256;
            if (idx < C_ * V_) xs2[idx] = px[rr];
        }
        __syncthreads();

        if (tid < 240) {
            u64 acc[4][5];
            #pragma unroll
            for (int jj = 0; jj < 4; jj++)
                #pragma unroll
                for (int k = 0; k < 5; k++) acc[jj][k] = 0ull;

            const float* wbase = WdT + (sZ << 12) + ogZ * 4;
            const u64*   xbase = xs2 + vgZ * 5;
            #pragma unroll 4
            for (int c = 0; c < C_; c++) {
                float4 w4 = *(const float4*)(wbase + (c << 6));
                u64 w0 = bcast2(w4.x), w1 = bcast2(w4.y);
                u64 w2 = bcast2(w4.z), w3 = bcast2(w4.w);
                const u64* xc = xbase + c * V_;
                #pragma unroll
                for (int k = 0; k < 5; k++) {
                    u64 xv = xc[k];
                    acc[0][k] = ffma2(w0, xv, acc[0][k]);
                    acc[1][k] = ffma2(w1, xv, acc[1][k]);
                    acc[2][k] = ffma2(w2, xv, acc[2][k]);
                    acc[3][k] = ffma2(w3, xv, acc[3][k]);
                }
            }
            #pragma unroll
            for (int k = 0; k < 5; k++) {
                u64* zp = zs2 + ((sZ * V_ + vgZ * 5 + k) << 6) + ogZ * 4;
                ulonglong2 p0; p0.x = acc[0][k]; p0.y = acc[1][k];
                ulonglong2 p1; p1.x = acc[2][k]; p1.y = acc[3][k];
                *(ulonglong2*)(zp)     = p0;
                *(ulonglong2*)(zp + 2) = p1;
            }
        }

        {
            int jn = j + nblk;
            if (jn < NITEMS) {
                int n2 = jn / NPAIR, t2 = (jn % NPAIR) * 2;
                const float* xb = x + (n2 * C_ * T_ + t2) * V_;
                #pragma unroll
                for (int rr = 0; rr < 7; rr++) {
                    int idx = tid + rr * 256;
                    if (idx < C_ * V_) {
                        int c = idx / V_, v = idx % V_;
                        const float* gp = xb + c * (T_ * V_) + v;
                        px[rr] = pack2(gp[0], gp[V_]);
                    }
                }
            }
        }
        __syncthreads();

        if (tid < 160) {
            const u64* abase = g_Aa2 + n * (S_ * V_ * V_) + wgY * 5;
            u64 acc[2][5];
            #pragma unroll
            for (int jj = 0; jj < 2; jj++)
                #pragma unroll
                for (int k = 0; k < 5; k++) acc[jj][k] = 0ull;

            #pragma unroll 5
            for (int sv = 0; sv < S_ * V_; sv++) {
                ulonglong2 z2 = *(const ulonglong2*)(zs2 + (sv << 6) + ogY * 2);
                const u64* ar = abase + sv * V_;
                #pragma unroll
                for (int k = 0; k < 5; k++) {
                    u64 aw = ar[k];
                    acc[0][k] = ffma2(z2.x, aw, acc[0][k]);
                    acc[1][k] = ffma2(z2.y, aw, acc[1][k]);
                }
            }
            #pragma unroll
            for (int jj = 0; jj < 2; jj++) {
                int o = ogY * 2 + jj;
                float sc = jj ? sc1 : sc0;
                float sh = jj ? sh1 : sh0;
                float* op = out + ((n * C_ + o) * T_ + t) * V_ + wgY * 5;
                const u64* xr = xs2 + o * V_ + wgY * 5;
                #pragma unroll
                for (int k = 0; k < 5; k++) {
                    float alo, ahi, xlo, xhi;
                    unpack2(acc[jj][k], alo, ahi);
                    unpack2(xr[k], xlo, xhi);
                    op[k]      = fmaxf(fmaf(sc, alo, sh) + xlo, 0.0f);
                    op[k + V_] = fmaxf(fmaf(sc, ahi, sh) + xhi, 0.0f);
                }
            }
        }
        buf ^= 1;
    }
}

// ---------------------------------------------------------------------------
extern "C" void kernel_launch(void* const* d_in, const int* in_sizes, int n_in,
                              void* d_out, int out_size)
{
    const float* x        = (const float*)d_in[0];
    const float* A        = (const float*)d_in[1];
    const float* alpha    = (const float*)d_in[2];
    const float* conv_a_w = (const float*)d_in[3];
    const float* conv_a_b = (const float*)d_in[4];
    const float* conv_b_w = (const float*)d_in[5];
    const float* conv_b_b = (const float*)d_in[6];
    const float* bn_a_g   = (const float*)d_in[7];
    const float* bn_a_be  = (const float*)d_in[8];
    const float* bn_a_m   = (const float*)d_in[9];
    const float* bn_a_v   = (const float*)d_in[10];
    const float* bn_b_g   = (const float*)d_in[11];
    const float* bn_b_be  = (const float*)d_in[12];
    const float* bn_b_m   = (const float*)d_in[13];
    const float* bn_b_v   = (const float*)d_in[14];
    const float* conv_d_w = (const float*)d_in[15];
    const float* conv_d_b = (const float*)d_in[16];
    const float* bn_g     = (const float*)d_in[17];
    const float* bn_be    = (const float*)d_in[18];
    const float* bn_m     = (const float*)d_in[19];
    const float* bn_v     = (const float*)d_in[20];
    float* out            = (float*)d_out;

    int nsm = 148;
    cudaDeviceGetAttribute(&nsm, cudaDevAttrMultiProcessorCount, 0);

    cudaFuncSetAttribute(k1_conv_M, cudaFuncAttributeMaxDynamicSharedMemorySize, SMEM1);
    cudaFuncSetAttribute(k3_out, cudaFuncAttributeMaxDynamicSharedMemorySize, SMEM3);

    dim3 g1(TCH1, S_, N_);
    k1_conv_M<<<g1, 160, SMEM1>>>(x, conv_a_w, conv_a_b, conv_b_w, conv_b_b,
                                  bn_a_g, bn_a_be, bn_a_m, bn_a_v,
                                  bn_b_g, bn_b_be, bn_b_m, bn_b_v);

    k2_adp<<<N_, 256>>>(A, alpha);

    k3_out<<<2 * nsm, 256, SMEM3>>>(x, conv_d_w, conv_d_b,
                                    bn_g, bn_be, bn_m, bn_v, out);
}

// round 6
// speedup vs baseline: 1.0961x; 1.0961x over previous
#include <cuda_runtime.h>

// ---------------------------------------------------------------------------
// unit_aagcn: N=64, C=OC=64, T=300, V=25, S=3, IC=16
// FFMA2-packed. R4 base + k1 padded-b2 vector M-phase + k3 chunked partition.
// ---------------------------------------------------------------------------

#define N_  64
#define C_  64
#define T_  300
#define V_  25
#define S_  3
#define IC_ 16

#define TCH1 3           // K1 t-chunks (100 t per block, 4 at a time)
#define T1   (T_ / TCH1) // 100
#define NPAIR (T_ / 2)   // 150 t-pairs per n
#define NITEMS (N_ * NPAIR) // 9600 k3 work items
#define BROW 30          // padded b2 row (u64) : w-groups at wg*6, 16B aligned

typedef unsigned long long u64;

__device__ float g_Mpart[N_ * S_ * TCH1 * V_ * V_];
__device__ u64   g_Aa2[N_ * S_ * V_ * V_];   // [n][s][v][w] {a,a}

__device__ __forceinline__ u64 pack2(float lo, float hi) {
    u64 r; asm("mov.b64 %0, {%1, %2};" : "=l"(r) : "f"(lo), "f"(hi)); return r;
}
__device__ __forceinline__ u64 bcast2(float v) {
    u64 r; asm("mov.b64 %0, {%1, %1};" : "=l"(r) : "f"(v)); return r;
}
__device__ __forceinline__ void unpack2(u64 p, float& lo, float& hi) {
    asm("mov.b64 {%0, %1}, %2;" : "=f"(lo), "=f"(hi) : "l"(p));
}
__device__ __forceinline__ u64 ffma2(u64 a, u64 b, u64 c) {
    u64 d; asm("fma.rn.f32x2 %0, %1, %2, %3;" : "=l"(d) : "l"(a), "l"(b), "l"(c));
    return d;
}
__device__ __forceinline__ float tanh_hw(float x) {
    float y; asm("tanh.approx.f32 %0, %1;" : "=f"(y) : "f"(x)); return y;
}

// ---------------------------------------------------------------------------
// K1: one block per (t-chunk, s, n). 160 threads. 4 t per iteration.
// ---------------------------------------------------------------------------
__global__ void __launch_bounds__(160, 4)
k1_conv_M(const float* __restrict__ x,
          const float* __restrict__ wa, const float* __restrict__ ba,
          const float* __restrict__ wb, const float* __restrict__ bb,
          const float* __restrict__ ga, const float* __restrict__ bea,
          const float* __restrict__ ma, const float* __restrict__ va,
          const float* __restrict__ gb, const float* __restrict__ beb,
          const float* __restrict__ mb, const float* __restrict__ vb)
{
    const int tc = blockIdx.x;
    const int s  = blockIdx.y;
    const int n  = blockIdx.z;
    const int tid = threadIdx.x;

    __shared__ alignas(16) u64 Wa2[C_ * IC_];      // [c][i]  {w,w}
    __shared__ alignas(16) u64 Wb2[C_ * IC_];
    __shared__ float sA[IC_], cA[IC_], sB[IC_], cB[IC_];
    __shared__ alignas(16) u64 xs2[C_ * 50];       // [c][pr(2)*25+v] t-pairs
    __shared__ alignas(16) u64 a2[2 * IC_ * V_];   // [p][i][v]
    __shared__ alignas(16) u64 b2[2 * IC_ * BROW]; // [p][i][wg*6+k] padded

    for (int idx = tid; idx < IC_ * C_; idx += 160) {
        int i = idx / C_, c = idx % C_;
        Wa2[c * IC_ + i] = bcast2(wa[(s * IC_ + i) * C_ + c]);
        Wb2[c * IC_ + i] = bcast2(wb[(s * IC_ + i) * C_ + c]);
    }
    if (tid < IC_) {
        int i = tid;
        float sa = ga[s * IC_ + i] * rsqrtf(va[s * IC_ + i] + 1e-5f);
        sA[i] = sa;
        cA[i] = sa * (ba[s * IC_ + i] - ma[s * IC_ + i]) + bea[s * IC_ + i];
        float sb = gb[s * IC_ + i] * rsqrtf(vb[s * IC_ + i] + 1e-5f);
        sB[i] = sb;
        cB[i] = sb * (bb[s * IC_ + i] - mb[s * IC_ + i]) + beb[s * IC_ + i];
    }

    const int pr = tid / 80;
    const int r  = tid % 80;
    const int ii = r & 15;
    const int vg = r >> 4;
    const int vv = tid / 5;
    const int wg = tid % 5;

    u64 m2[5] = {0ull, 0ull, 0ull, 0ull, 0ull};
    const int t0 = tc * T1;

    // prefetch first 4-t group into registers (20 u64 per thread)
    u64 px[20];
    {
        const int t = t0;
        #pragma unroll
        for (int rr = 0; rr < 20; rr++) {
            int idx = tid + rr * 160;
            int c = idx / 50, rm = idx % 50;
            int p = rm / 25, v = rm % 25;
            const float* gp = x + ((n * C_ + c) * T_ + t + 2 * p) * V_ + v;
            px[rr] = pack2(gp[0], gp[V_]);
        }
    }

    for (int tp = 0; tp < T1; tp += 4) {
        #pragma unroll
        for (int rr = 0; rr < 20; rr++)
            xs2[tid + rr * 160] = px[rr];
        __syncthreads();

        {
            u64 acca[5] = {0,0,0,0,0};
            u64 accb[5] = {0,0,0,0,0};
            const u64* xrow = xs2 + pr * 25 + vg * 5;
            #pragma unroll 8
            for (int c = 0; c < C_; c++) {
                u64 wa2 = Wa2[c * IC_ + ii];
                u64 wb2 = Wb2[c * IC_ + ii];
                #pragma unroll
                for (int k = 0; k < 5; k++) {
                    u64 xv = xrow[c * 50 + k];
                    acca[k] = ffma2(wa2, xv, acca[k]);
                    accb[k] = ffma2(wb2, xv, accb[k]);
                }
            }
            float sa = sA[ii], ca = cA[ii], sb = sB[ii], cb = cB[ii];
            u64* ap = a2 + (pr * IC_ + ii) * V_ + vg * 5;
            u64* bp = b2 + (pr * IC_ + ii) * BROW + vg * 6;
            u64 bv[5];
            #pragma unroll
            for (int k = 0; k < 5; k++) {
                float lo, hi;
                unpack2(acca[k], lo, hi);
                ap[k] = pack2(tanh_hw(fmaf(sa, lo, ca)), tanh_hw(fmaf(sa, hi, ca)));
                unpack2(accb[k], lo, hi);
                bv[k] = pack2(tanh_hw(fmaf(sb, lo, cb)), tanh_hw(fmaf(sb, hi, cb)));
            }
            ulonglong2 b01; b01.x = bv[0]; b01.y = bv[1];
            ulonglong2 b23; b23.x = bv[2]; b23.y = bv[3];
            *(ulonglong2*)(bp)     = b01;
            *(ulonglong2*)(bp + 2) = b23;
            bp[4] = bv[4];
        }
        __syncthreads();

        // prefetch next group's x while M phase runs
        if (tp + 4 < T1) {
            const int t = t0 + tp + 4;
            #pragma unroll
            for (int rr = 0; rr < 20; rr++) {
                int idx = tid + rr * 160;
                int c = idx / 50, rm = idx % 50;
                int p = rm / 25, v = rm % 25;
                const float* gp = x + ((n * C_ + c) * T_ + t + 2 * p) * V_ + v;
                px[rr] = pack2(gp[0], gp[V_]);
            }
        }

        if (tid < 125) {
            #pragma unroll
            for (int p = 0; p < 2; p++) {
                const u64* ap    = a2 + p * IC_ * V_ + vv;
                const u64* bbase = b2 + p * IC_ * BROW + wg * 6;
                #pragma unroll 4
                for (int i = 0; i < IC_; i++) {
                    u64 av = ap[i * V_];
                    ulonglong2 b01 = *(const ulonglong2*)(bbase + i * BROW);
                    ulonglong2 b23 = *(const ulonglong2*)(bbase + i * BROW + 2);
                    u64 b4 = bbase[i * BROW + 4];
                    m2[0] = ffma2(av, b01.x, m2[0]);
                    m2[1] = ffma2(av, b01.y, m2[1]);
                    m2[2] = ffma2(av, b23.x, m2[2]);
                    m2[3] = ffma2(av, b23.y, m2[3]);
                    m2[4] = ffma2(av, b4,    m2[4]);
                }
            }
        }
    }

    if (tid < 125) {
        float* dst = g_Mpart + ((((n * S_ + s) * TCH1 + tc) * V_ + vv) * V_) + wg * 5;
        #pragma unroll
        for (int k = 0; k < 5; k++) {
            float lo, hi;
            unpack2(m2[k], lo, hi);
            dst[k] = lo + hi;
        }
    }
}

// ---------------------------------------------------------------------------
// k2: A_adp[n][s][v][w] duplicated u64 from M partials. One block per n.
// ---------------------------------------------------------------------------
__global__ void __launch_bounds__(256)
k2_adp(const float* __restrict__ A, const float* __restrict__ alpha)
{
    const int n = blockIdx.x;
    const float al = alpha[0];
    for (int idx = threadIdx.x; idx < S_ * V_ * V_; idx += 256) {
        const float* mp = g_Mpart + (n * S_ * TCH1) * (V_ * V_) +
                          (idx / (V_ * V_)) * TCH1 * (V_ * V_) + (idx % (V_ * V_));
        float msum = 0.f;
        #pragma unroll
        for (int p = 0; p < TCH1; p++) msum += mp[p * (V_ * V_)];
        float val = A[idx] + tanhf(msum * (1.0f / (IC_ * T_))) * al;
        g_Aa2[n * (S_ * V_ * V_) + idx] = bcast2(val);
    }
}

// ---------------------------------------------------------------------------
// K3: persistent blocks, CONTIGUOUS item chunks (n-locality for Aa L1 reuse).
// smem: WdT 49152 + xs2[2] 25600 + zs2 38400 = 113152 B -> 2 CTAs/SM.
// ---------------------------------------------------------------------------
#define OFF_WDT   0
#define OFF_XS    49152
#define OFF_ZS    (49152 + 25600)
#define SMEM3     (OFF_ZS + 38400)

__global__ void __launch_bounds__(256, 2)
k3_out(const float* __restrict__ x,
       const float* __restrict__ wd, const float* __restrict__ bd,
       const float* __restrict__ bng, const float* __restrict__ bnb,
       const float* __restrict__ bnm, const float* __restrict__ bnv,
       float* __restrict__ out)
{
    extern __shared__ char smem[];
    float* WdT = (float*)(smem + OFF_WDT);   // [s][c][o]
    u64*   xsA = (u64*)  (smem + OFF_XS);    // two buffers of [c][v] t-pairs
    u64*   zs2 = (u64*)  (smem + OFF_ZS);    // [(s*25+v)][o] packed

    const int tid  = threadIdx.x;
    const int nblk = gridDim.x;

    // contiguous chunk [lo, hi) with remainder spread over low blocks
    const int base = NITEMS / nblk;
    const int rem  = NITEMS % nblk;
    const int b    = blockIdx.x;
    const int lo   = b * base + (b < rem ? b : rem);
    const int hi   = lo + base + (b < rem ? 1 : 0);
    if (lo >= hi) return;

    for (int idx = tid; idx < S_ * C_ * C_; idx += 256) {
        int s = idx >> 12, o = (idx >> 6) & 63, c = idx & 63;
        WdT[(s << 12) + (c << 6) + o] = wd[idx];
    }

    const int sZ  = tid / 80;
    const int rZ  = tid % 80;
    const int ogZ = rZ & 15;
    const int vgZ = rZ >> 4;
    const int ogY = tid & 31;
    const int wgY = tid >> 5;

    float sc0 = 0.f, sh0 = 0.f, sc1 = 0.f, sh1 = 0.f;
    if (tid < 160) {
        int o0 = ogY * 2, o1 = o0 + 1;
        sc0 = bng[o0] * rsqrtf(bnv[o0] + 1e-5f);
        sh0 = bnb[o0] + sc0 * (bd[o0] + bd[C_ + o0] + bd[2 * C_ + o0] - bnm[o0]);
        sc1 = bng[o1] * rsqrtf(bnv[o1] + 1e-5f);
        sh1 = bnb[o1] + sc1 * (bd[o1] + bd[C_ + o1] + bd[2 * C_ + o1] - bnm[o1]);
    }

    // prefetch first item's x into registers
    u64 px[7];
    {
        int n = lo / NPAIR, t = (lo % NPAIR) * 2;
        const float* xb = x + (n * C_ * T_ + t) * V_;
        #pragma unroll
        for (int rr = 0; rr < 7; rr++) {
            int idx = tid + rr * 256;
            if (idx < C_ * V_) {
                int c = idx / V_, v = idx % V_;
                const float* gp = xb + c * (T_ * V_) + v;
                px[rr] = pack2(gp[0], gp[V_]);
            }
        }
    }

    int buf = 0;
    for (int j = lo; j < hi; j++) {
        const int n = j / NPAIR;
        const int t = (j % NPAIR) * 2;
        u64* xs2 = xsA + buf * (C_ * V_);

        #pragma unroll
        for (int rr = 0; rr < 7; rr++) {
            int idx = tid + rr * 256;
            if (idx < C_ * V_) xs2[idx] = px[rr];
        }
        __syncthreads();   // xs2 ready; zs2 free (prev Y done)

        // phase Z: z[s][v][o] = sum_c Wd[s][o][c] * x[c][v]  (packed t-pair)
        if (tid < 240) {
            u64 acc[4][5];
            #pragma unroll
            for (int jj = 0; jj < 4; jj++)
                #pragma unroll
                for (int k = 0; k < 5; k++) acc[jj][k] = 0ull;

            const float* wbase = WdT + (sZ << 12) + ogZ * 4;
            const u64*   xbase = xs2 + vgZ * 5;
            #pragma unroll 4
            for (int c = 0; c < C_; c++) {
                float4 w4 = *(const float4*)(wbase + (c << 6));
                u64 w0 = bcast2(w4.x), w1 = bcast2(w4.y);
                u64 w2 = bcast2(w4.z), w3 = bcast2(w4.w);
                const u64* xc = xbase + c * V_;
                #pragma unroll
                for (int k = 0; k < 5; k++) {
                    u64 xv = xc[k];
                    acc[0][k] = ffma2(w0, xv, acc[0][k]);
                    acc[1][k] = ffma2(w1, xv, acc[1][k]);
                    acc[2][k] = ffma2(w2, xv, acc[2][k]);
                    acc[3][k] = ffma2(w3, xv, acc[3][k]);
                }
            }
            #pragma unroll
            for (int k = 0; k < 5; k++) {
                u64* zp = zs2 + ((sZ * V_ + vgZ * 5 + k) << 6) + ogZ * 4;
                ulonglong2 p0; p0.x = acc[0][k]; p0.y = acc[1][k];
                ulonglong2 p1; p1.x = acc[2][k]; p1.y = acc[3][k];
                *(ulonglong2*)(zp)     = p0;
                *(ulonglong2*)(zp + 2) = p1;
            }
        }

        // prefetch next item's x while Z finishes / Y runs
        {
            int jn = j + 1;
            if (jn < hi) {
                int n2 = jn / NPAIR, t2 = (jn % NPAIR) * 2;
                const float* xb = x + (n2 * C_ * T_ + t2) * V_;
                #pragma unroll
                for (int rr = 0; rr < 7; rr++) {
                    int idx = tid + rr * 256;
                    if (idx < C_ * V_) {
                        int c = idx / V_, v = idx % V_;
                        const float* gp = xb + c * (T_ * V_) + v;
                        px[rr] = pack2(gp[0], gp[V_]);
                    }
                }
            }
        }
        __syncthreads();   // zs2 ready

        // phase Y: y[o][w] = sum_{s,v} z[s][v][o] * Aa[s][v][w] + epilogue
        if (tid < 160) {
            const u64* abase = g_Aa2 + n * (S_ * V_ * V_) + wgY * 5;
            u64 acc[2][5];
            #pragma unroll
            for (int jj = 0; jj < 2; jj++)
                #pragma unroll
                for (int k = 0; k < 5; k++) acc[jj][k] = 0ull;

            #pragma unroll 5
            for (int sv = 0; sv < S_ * V_; sv++) {
                ulonglong2 z2 = *(const ulonglong2*)(zs2 + (sv << 6) + ogY * 2);
                const u64* ar = abase + sv * V_;   // lane-uniform address
                #pragma unroll
                for (int k = 0; k < 5; k++) {
                    u64 aw = ar[k];
                    acc[0][k] = ffma2(z2.x, aw, acc[0][k]);
                    acc[1][k] = ffma2(z2.y, aw, acc[1][k]);
                }
            }
            #pragma unroll
            for (int jj = 0; jj < 2; jj++) {
                int o = ogY * 2 + jj;
                float sc = jj ? sc1 : sc0;
                float sh = jj ? sh1 : sh0;
                float* op = out + ((n * C_ + o) * T_ + t) * V_ + wgY * 5;
                const u64* xr = xs2 + o * V_ + wgY * 5;
                #pragma unroll
                for (int k = 0; k < 5; k++) {
                    float alo, ahi, xlo, xhi;
                    unpack2(acc[jj][k], alo, ahi);
                    unpack2(xr[k], xlo, xhi);
                    op[k]      = fmaxf(fmaf(sc, alo, sh) + xlo, 0.0f);
                    op[k + V_] = fmaxf(fmaf(sc, ahi, sh) + xhi, 0.0f);
                }
            }
        }
        buf ^= 1;
    }
}

// ---------------------------------------------------------------------------
extern "C" void kernel_launch(void* const* d_in, const int* in_sizes, int n_in,
                              void* d_out, int out_size)
{
    const float* x        = (const float*)d_in[0];
    const float* A        = (const float*)d_in[1];
    const float* alpha    = (const float*)d_in[2];
    const float* conv_a_w = (const float*)d_in[3];
    const float* conv_a_b = (const float*)d_in[4];
    const float* conv_b_w = (const float*)d_in[5];
    const float* conv_b_b = (const float*)d_in[6];
    const float* bn_a_g   = (const float*)d_in[7];
    const float* bn_a_be  = (const float*)d_in[8];
    const float* bn_a_m   = (const float*)d_in[9];
    const float* bn_a_v   = (const float*)d_in[10];
    const float* bn_b_g   = (const float*)d_in[11];
    const float* bn_b_be  = (const float*)d_in[12];
    const float* bn_b_m   = (const float*)d_in[13];
    const float* bn_b_v   = (const float*)d_in[14];
    const float* conv_d_w = (const float*)d_in[15];
    const float* conv_d_b = (const float*)d_in[16];
    const float* bn_g     = (const float*)d_in[17];
    const float* bn_be    = (const float*)d_in[18];
    const float* bn_m     = (const float*)d_in[19];
    const float* bn_v     = (const float*)d_in[20];
    float* out            = (float*)d_out;

    int nsm = 148;
    cudaDeviceGetAttribute(&nsm, cudaDevAttrMultiProcessorCount, 0);

    cudaFuncSetAttribute(k3_out, cudaFuncAttributeMaxDynamicSharedMemorySize, SMEM3);

    dim3 g1(TCH1, S_, N_);
    k1_conv_M<<<g1, 160>>>(x, conv_a_w, conv_a_b, conv_b_w, conv_b_b,
                           bn_a_g, bn_a_be, bn_a_m, bn_a_v,
                           bn_b_g, bn_b_be, bn_b_m, bn_b_v);

    k2_adp<<<N_, 256>>>(A, alpha);

    k3_out<<<2 * nsm, 256, SMEM3>>>(x, conv_d_w, conv_d_b,
                                    bn_g, bn_be, bn_m, bn_v, out);
}